// round 1
// baseline (speedup 1.0000x reference)
#include <cuda_runtime.h>
#include <cuda_bf16.h>
#include <math.h>

#define N_NODES 100000
#define N_EDGES 640000
#define IN_FEATS 256
#define HEADS 4
#define OUT_FEATS 32
#define HD (HEADS * OUT_FEATS)   // 128
#define NEG_SLOPE 0.2f

// ---------------- scratch (no allocs allowed) ----------------
__device__ float    g_ft[(size_t)N_NODES * HD];        // 51.2 MB
__device__ float    g_el[N_NODES * HEADS];
__device__ float    g_er[N_NODES * HEADS];
__device__ float    g_e [(size_t)N_EDGES * HEADS];     // logits, then ex
__device__ float    g_a [(size_t)N_EDGES * HEADS];     // attention coeffs
__device__ unsigned g_mbits[N_NODES * HEADS];
__device__ float    g_denom[N_NODES * HEADS];
__device__ int      g_counts[N_NODES];
__device__ int      g_offsets[N_NODES + 1];
__device__ int      g_cursor[N_NODES];
__device__ int      g_block_sums[128];
__device__ int      g_edge_idx[N_EDGES];

// monotonic float<->uint order-preserving encode for atomicMax
__device__ __forceinline__ unsigned f_enc(float f) {
    unsigned u = __float_as_uint(f);
    return (u & 0x80000000u) ? ~u : (u | 0x80000000u);
}
__device__ __forceinline__ float f_dec(unsigned u) {
    return (u & 0x80000000u) ? __uint_as_float(u & 0x7FFFFFFFu)
                             : __uint_as_float(~u);
}

// ---------------- init ----------------
__global__ void init_kernel() {
    int i = blockIdx.x * blockDim.x + threadIdx.x;
    if (i < N_NODES * HEADS) { g_mbits[i] = 0u; g_denom[i] = 0.0f; }
    if (i < N_NODES) g_counts[i] = 0;
}

// ---------------- GEMM: ft = feat[100000,256] @ W[256,128] ----------------
// 128x128 block tile, K-chunks of 16, 256 threads, 8x8 per thread.
__global__ __launch_bounds__(256) void gemm_kernel(
    const float* __restrict__ A, const float* __restrict__ B,
    float* __restrict__ C)
{
    __shared__ float As[16][132];   // transposed: As[k][m]
    __shared__ float Bs[16][132];
    const int tid = threadIdx.x;
    const int tx = tid & 15, ty = tid >> 4;
    const int blockM = blockIdx.x * 128;

    float acc[8][8];
#pragma unroll
    for (int i = 0; i < 8; i++)
#pragma unroll
        for (int j = 0; j < 8; j++) acc[i][j] = 0.0f;

    for (int k0 = 0; k0 < IN_FEATS; k0 += 16) {
        // load A tile: 128 rows x 16 k, transposed into As
#pragma unroll
        for (int it = 0; it < 2; it++) {
            int f = tid + it * 256;           // 0..511 (float4 id)
            int row = f >> 2;                 // 0..127
            int kq  = (f & 3) * 4;            // 0,4,8,12
            int grow = blockM + row;
            float4 v = make_float4(0.f, 0.f, 0.f, 0.f);
            if (grow < N_NODES)
                v = *(const float4*)(A + (size_t)grow * IN_FEATS + k0 + kq);
            As[kq + 0][row] = v.x; As[kq + 1][row] = v.y;
            As[kq + 2][row] = v.z; As[kq + 3][row] = v.w;
        }
        // load B tile: 16 k x 128 cols
#pragma unroll
        for (int it = 0; it < 2; it++) {
            int f = tid + it * 256;
            int kr = f >> 5;                  // 0..15
            int cq = (f & 31) * 4;            // 0..124
            float4 v = *(const float4*)(B + (size_t)(k0 + kr) * HD + cq);
            *(float4*)&Bs[kr][cq] = v;
        }
        __syncthreads();
#pragma unroll
        for (int k = 0; k < 16; k++) {
            float ra[8], rb[8];
#pragma unroll
            for (int i = 0; i < 8; i++) ra[i] = As[k][ty * 8 + i];
#pragma unroll
            for (int j = 0; j < 8; j++) rb[j] = Bs[k][tx * 8 + j];
#pragma unroll
            for (int i = 0; i < 8; i++)
#pragma unroll
                for (int j = 0; j < 8; j++) acc[i][j] += ra[i] * rb[j];
        }
        __syncthreads();
    }
#pragma unroll
    for (int i = 0; i < 8; i++) {
        int row = blockM + ty * 8 + i;
        if (row >= N_NODES) break;
        float* crow = C + (size_t)row * HD + tx * 8;
        *(float4*)(crow + 0) = make_float4(acc[i][0], acc[i][1], acc[i][2], acc[i][3]);
        *(float4*)(crow + 4) = make_float4(acc[i][4], acc[i][5], acc[i][6], acc[i][7]);
    }
}

// ---------------- el/er: per-node dot with attn_l/attn_r ----------------
// one warp per node; lane l handles floats [4l,4l+4); head = l>>3
__global__ void elr_kernel(const float* __restrict__ attn_l,
                           const float* __restrict__ attn_r)
{
    int warp = (blockIdx.x * blockDim.x + threadIdx.x) >> 5;
    int lane = threadIdx.x & 31;
    if (warp >= N_NODES) return;
    int h = lane >> 3, db = (lane & 7) * 4;
    float4 al = *(const float4*)(attn_l + h * OUT_FEATS + db);
    float4 ar = *(const float4*)(attn_r + h * OUT_FEATS + db);
    float4 f  = *(const float4*)(g_ft + (size_t)warp * HD + lane * 4);
    float sl = f.x * al.x + f.y * al.y + f.z * al.z + f.w * al.w;
    float sr = f.x * ar.x + f.y * ar.y + f.z * ar.z + f.w * ar.w;
#pragma unroll
    for (int o = 4; o >= 1; o >>= 1) {
        sl += __shfl_xor_sync(0xffffffffu, sl, o);
        sr += __shfl_xor_sync(0xffffffffu, sr, o);
    }
    if ((lane & 7) == 0) {
        g_el[warp * HEADS + h] = sl;
        g_er[warp * HEADS + h] = sr;
    }
}

// ---------------- edge pass 1: logits + leaky + segment max + histogram ----
__global__ void edge1_kernel(const int* __restrict__ src,
                             const int* __restrict__ dst)
{
    int e = blockIdx.x * blockDim.x + threadIdx.x;
    if (e >= N_EDGES) return;
    int s = src[e], d = dst[e];
    atomicAdd(&g_counts[d], 1);
#pragma unroll
    for (int h = 0; h < HEADS; h++) {
        float v = g_el[s * HEADS + h] + g_er[d * HEADS + h];
        v = v > 0.0f ? v : NEG_SLOPE * v;
        g_e[(size_t)e * HEADS + h] = v;
        atomicMax(&g_mbits[d * HEADS + h], f_enc(v));
    }
}

// ---------------- edge pass 2: exp(e - m) + segment sum -------------------
__global__ void edge2_kernel(const int* __restrict__ dst)
{
    int e = blockIdx.x * blockDim.x + threadIdx.x;
    if (e >= N_EDGES) return;
    int d = dst[e];
#pragma unroll
    for (int h = 0; h < HEADS; h++) {
        float m = f_dec(g_mbits[d * HEADS + h]);
        float ex = expf(g_e[(size_t)e * HEADS + h] - m);
        g_e[(size_t)e * HEADS + h] = ex;
        atomicAdd(&g_denom[d * HEADS + h], ex);
    }
}

// ---------------- edge pass 3: a = ex / denom ------------------------------
__global__ void edge3_kernel(const int* __restrict__ dst,
                             float* __restrict__ a_out, int has_a)
{
    int e = blockIdx.x * blockDim.x + threadIdx.x;
    if (e >= N_EDGES) return;
    int d = dst[e];
#pragma unroll
    for (int h = 0; h < HEADS; h++) {
        float a = g_e[(size_t)e * HEADS + h] / g_denom[d * HEADS + h];
        g_a[(size_t)e * HEADS + h] = a;
        if (has_a) a_out[(size_t)e * HEADS + h] = a;
    }
}

// ---------------- scan (counts -> exclusive offsets) ----------------------
__global__ void scan1_kernel() {
    __shared__ int s[1024];
    int t = threadIdx.x;
    int idx = blockIdx.x * 1024 + t;
    int v = (idx < N_NODES) ? g_counts[idx] : 0;
    s[t] = v;
    __syncthreads();
#pragma unroll
    for (int off = 1; off < 1024; off <<= 1) {
        int u = (t >= off) ? s[t - off] : 0;
        __syncthreads();
        s[t] += u;
        __syncthreads();
    }
    if (idx < N_NODES) g_offsets[idx] = s[t] - v;  // block-local exclusive
    if (t == 1023) g_block_sums[blockIdx.x] = s[t];
}

__global__ void scan2_kernel(int nblocks) {
    __shared__ int s[128];
    int t = threadIdx.x;
    int v = (t < nblocks) ? g_block_sums[t] : 0;
    s[t] = v;
    __syncthreads();
#pragma unroll
    for (int off = 1; off < 128; off <<= 1) {
        int u = (t >= off) ? s[t - off] : 0;
        __syncthreads();
        s[t] += u;
        __syncthreads();
    }
    if (t < nblocks) g_block_sums[t] = s[t] - v;  // exclusive
}

__global__ void scan3_kernel() {
    int idx = blockIdx.x * 1024 + threadIdx.x;
    if (idx < N_NODES) {
        int off = g_offsets[idx] + g_block_sums[blockIdx.x];
        g_offsets[idx] = off;
        g_cursor[idx] = off;
    }
    if (idx == 0) g_offsets[N_NODES] = N_EDGES;
}

// ---------------- CSR scatter ---------------------------------------------
__global__ void scatter_kernel(const int* __restrict__ dst) {
    int e = blockIdx.x * blockDim.x + threadIdx.x;
    if (e >= N_EDGES) return;
    int pos = atomicAdd(&g_cursor[dst[e]], 1);
    g_edge_idx[pos] = e;
}

// ---------------- aggregation: rst[v] = sum a * ft[src] --------------------
// one warp per node; lane l owns floats [4l,4l+4) of the 128-wide row.
__global__ void agg_kernel(const int* __restrict__ src,
                           float* __restrict__ rst)
{
    int warp = (blockIdx.x * blockDim.x + threadIdx.x) >> 5;
    int lane = threadIdx.x & 31;
    if (warp >= N_NODES) return;
    int h = lane >> 3;
    int p0 = g_offsets[warp];
    int p1 = g_offsets[warp + 1];
    float4 acc = make_float4(0.f, 0.f, 0.f, 0.f);
    const float4* ft4 = (const float4*)g_ft;
    for (int p = p0; p < p1; p++) {
        int e = g_edge_idx[p];
        int s = src[e];
        float a = g_a[(size_t)e * HEADS + h];
        float4 f = ft4[(size_t)s * 32 + lane];
        acc.x += a * f.x; acc.y += a * f.y;
        acc.z += a * f.z; acc.w += a * f.w;
    }
    *(float4*)(rst + (size_t)warp * HD + lane * 4) = acc;
}

// ---------------- launch ----------------------------------------------------
extern "C" void kernel_launch(void* const* d_in, const int* in_sizes, int n_in,
                              void* d_out, int out_size)
{
    const float* feat   = (const float*)d_in[0];
    const float* W      = (const float*)d_in[1];
    const float* attn_l = (const float*)d_in[2];
    const float* attn_r = (const float*)d_in[3];
    const int*   src    = (const int*)d_in[4];
    const int*   dst    = (const int*)d_in[5];
    float* out = (float*)d_out;

    const int rst_elems = N_NODES * HD;
    const int has_a = (out_size >= rst_elems + N_EDGES * HEADS) ? 1 : 0;
    float* a_out = out + rst_elems;

    float* ft_dev;   cudaGetSymbolAddress((void**)&ft_dev, g_ft);

    // init
    init_kernel<<<(N_NODES * HEADS + 255) / 256, 256>>>();
    // gemm
    gemm_kernel<<<(N_NODES + 127) / 128, 256>>>(feat, W, ft_dev);
    // per-node logits
    elr_kernel<<<(N_NODES * 32 + 255) / 256, 256>>>(attn_l, attn_r);
    // edge passes
    int eb = (N_EDGES + 255) / 256;
    edge1_kernel<<<eb, 256>>>(src, dst);
    edge2_kernel<<<eb, 256>>>(dst);
    edge3_kernel<<<eb, 256>>>(dst, a_out, has_a);
    // CSR build
    int sb = (N_NODES + 1023) / 1024;      // 98
    scan1_kernel<<<sb, 1024>>>();
    scan2_kernel<<<1, 128>>>(sb);
    scan3_kernel<<<sb, 1024>>>();
    scatter_kernel<<<eb, 256>>>(dst);
    // aggregate
    agg_kernel<<<(N_NODES * 32 + 255) / 256, 256>>>(src, out);
}

// round 2
// speedup vs baseline: 1.6151x; 1.6151x over previous
#include <cuda_runtime.h>
#include <cuda_bf16.h>
#include <math.h>

#define N_NODES 100000
#define N_EDGES 640000
#define IN_FEATS 256
#define HEADS 4
#define OUT_FEATS 32
#define HD (HEADS * OUT_FEATS)   // 128
#define NEG_SLOPE 0.2f

// ---------------- scratch (no allocs allowed) ----------------
__device__ float    g_ft[(size_t)N_NODES * HD];        // 51.2 MB
__device__ float    g_el[N_NODES * HEADS];
__device__ float    g_er[N_NODES * HEADS];
__device__ float    g_e [(size_t)N_EDGES * HEADS];     // exp(logit)
__device__ float    g_denom[N_NODES * HEADS];
__device__ int      g_counts[N_NODES];
__device__ int      g_offsets[N_NODES + 1];
__device__ int      g_cursor[N_NODES];
__device__ int      g_block_sums[128];
__device__ int      g_edge_idx[N_EDGES];

// ---------------- init ----------------
__global__ void init_kernel() {
    int i = blockIdx.x * blockDim.x + threadIdx.x;
    if (i < N_NODES * HEADS) g_denom[i] = 0.0f;
    if (i < N_NODES) g_counts[i] = 0;
}

// ---------------- TF32 helpers ----------------
__device__ __forceinline__ float to_tf32(float x) {
    unsigned u;
    asm("cvt.rna.tf32.f32 %0, %1;" : "=r"(u) : "f"(x));
    return __uint_as_float(u);
}

__device__ __forceinline__ void mma_tf32(float* d, const unsigned* a,
                                         unsigned b0, unsigned b1) {
    asm volatile(
        "mma.sync.aligned.m16n8k8.row.col.f32.tf32.tf32.f32 "
        "{%0,%1,%2,%3}, {%4,%5,%6,%7}, {%8,%9}, {%0,%1,%2,%3};"
        : "+f"(d[0]), "+f"(d[1]), "+f"(d[2]), "+f"(d[3])
        : "r"(a[0]), "r"(a[1]), "r"(a[2]), "r"(a[3]), "r"(b0), "r"(b1));
}

// ---------------- GEMM: ft = feat[100000,256] @ W[256,128], TF32 MMA ------
// 128x128 block tile, BK=32, 256 threads = 8 warps in 4x2 grid (warp 32x64).
__global__ __launch_bounds__(256, 2) void gemm_tf32_kernel(
    const float* __restrict__ A, const float* __restrict__ B,
    float* __restrict__ C)
{
    __shared__ float As[128][36];   // row-major [m][k], pad 36 -> conflict-free frags
    __shared__ float Bs[32][136];   // [k][n],   pad 136 -> conflict-free frags
    const int tid  = threadIdx.x;
    const int warp = tid >> 5, lane = tid & 31;
    const int wm = warp >> 1, wn = warp & 1;      // warp tile origin (wm*32, wn*64)
    const int g = lane >> 2, c = lane & 3;
    const int blockM = blockIdx.x * 128;

    float acc[2][8][4];
#pragma unroll
    for (int i = 0; i < 2; i++)
#pragma unroll
        for (int j = 0; j < 8; j++)
#pragma unroll
            for (int r = 0; r < 4; r++) acc[i][j][r] = 0.0f;

    const int arow = tid >> 1;             // 0..127
    const int akq  = (tid & 1) * 16;       // 0 or 16
    const bool arow_ok = (blockM + arow) < N_NODES;

    for (int k0 = 0; k0 < IN_FEATS; k0 += 32) {
        // --- load A tile (rounded to tf32 once) ---
        const float* ap = A + (size_t)(blockM + arow) * IN_FEATS + k0 + akq;
#pragma unroll
        for (int i = 0; i < 4; i++) {
            float4 v = arow_ok ? *(const float4*)(ap + i * 4)
                               : make_float4(0.f, 0.f, 0.f, 0.f);
            As[arow][akq + i * 4 + 0] = to_tf32(v.x);
            As[arow][akq + i * 4 + 1] = to_tf32(v.y);
            As[arow][akq + i * 4 + 2] = to_tf32(v.z);
            As[arow][akq + i * 4 + 3] = to_tf32(v.w);
        }
        // --- load B tile ---
#pragma unroll
        for (int it = 0; it < 4; it++) {
            int f  = tid + it * 256;         // 0..1023 float4 id
            int kr = f >> 5;                 // 0..31
            int cq = (f & 31) * 4;           // 0..124
            float4 v = *(const float4*)(B + (size_t)(k0 + kr) * HD + cq);
            Bs[kr][cq + 0] = to_tf32(v.x);
            Bs[kr][cq + 1] = to_tf32(v.y);
            Bs[kr][cq + 2] = to_tf32(v.z);
            Bs[kr][cq + 3] = to_tf32(v.w);
        }
        __syncthreads();

#pragma unroll
        for (int ks = 0; ks < 4; ks++) {
            const int kb = ks * 8;
            unsigned afrag[2][4];
#pragma unroll
            for (int i = 0; i < 2; i++) {
                int r = wm * 32 + i * 16;
                afrag[i][0] = __float_as_uint(As[r + g    ][kb + c    ]);
                afrag[i][1] = __float_as_uint(As[r + g + 8][kb + c    ]);
                afrag[i][2] = __float_as_uint(As[r + g    ][kb + c + 4]);
                afrag[i][3] = __float_as_uint(As[r + g + 8][kb + c + 4]);
            }
#pragma unroll
            for (int j = 0; j < 8; j++) {
                int col = wn * 64 + j * 8 + g;
                unsigned b0 = __float_as_uint(Bs[kb + c    ][col]);
                unsigned b1 = __float_as_uint(Bs[kb + c + 4][col]);
                mma_tf32(acc[0][j], afrag[0], b0, b1);
                mma_tf32(acc[1][j], afrag[1], b0, b1);
            }
        }
        __syncthreads();
    }

    // --- epilogue: 64-bit stores, pairs are contiguous cols ---
#pragma unroll
    for (int i = 0; i < 2; i++) {
        int r0 = blockM + wm * 32 + i * 16 + g;
#pragma unroll
        for (int j = 0; j < 8; j++) {
            int cc = wn * 64 + j * 8 + c * 2;
            if (r0 < N_NODES)
                *(float2*)(C + (size_t)r0 * HD + cc) =
                    make_float2(acc[i][j][0], acc[i][j][1]);
            if (r0 + 8 < N_NODES)
                *(float2*)(C + (size_t)(r0 + 8) * HD + cc) =
                    make_float2(acc[i][j][2], acc[i][j][3]);
        }
    }
}

// ---------------- el/er: per-node dot with attn_l/attn_r ----------------
__global__ void elr_kernel(const float* __restrict__ attn_l,
                           const float* __restrict__ attn_r)
{
    int warp = (blockIdx.x * blockDim.x + threadIdx.x) >> 5;
    int lane = threadIdx.x & 31;
    if (warp >= N_NODES) return;
    int h = lane >> 3, db = (lane & 7) * 4;
    float4 al = *(const float4*)(attn_l + h * OUT_FEATS + db);
    float4 ar = *(const float4*)(attn_r + h * OUT_FEATS + db);
    float4 f  = *(const float4*)(g_ft + (size_t)warp * HD + lane * 4);
    float sl = f.x * al.x + f.y * al.y + f.z * al.z + f.w * al.w;
    float sr = f.x * ar.x + f.y * ar.y + f.z * ar.z + f.w * ar.w;
#pragma unroll
    for (int o = 4; o >= 1; o >>= 1) {
        sl += __shfl_xor_sync(0xffffffffu, sl, o);
        sr += __shfl_xor_sync(0xffffffffu, sr, o);
    }
    if ((lane & 7) == 0) {
        g_el[warp * HEADS + h] = sl;
        g_er[warp * HEADS + h] = sr;
    }
}

// ---- fused edge pass: logits + leaky + exp + denom atomics + histogram ----
// (segment-max subtraction removed: exp(e)/sum(exp(e)) is mathematically
//  identical and logits are O(1) here, so no overflow risk)
__global__ void edge_fused_kernel(const int* __restrict__ src,
                                  const int* __restrict__ dst)
{
    int e = blockIdx.x * blockDim.x + threadIdx.x;
    if (e >= N_EDGES) return;
    int s = src[e], d = dst[e];
    atomicAdd(&g_counts[d], 1);
    float4 el = *(const float4*)(g_el + (size_t)s * HEADS);
    float4 er = *(const float4*)(g_er + (size_t)d * HEADS);
    float4 v;
    v.x = el.x + er.x; v.y = el.y + er.y;
    v.z = el.z + er.z; v.w = el.w + er.w;
    v.x = v.x > 0.f ? v.x : NEG_SLOPE * v.x;
    v.y = v.y > 0.f ? v.y : NEG_SLOPE * v.y;
    v.z = v.z > 0.f ? v.z : NEG_SLOPE * v.z;
    v.w = v.w > 0.f ? v.w : NEG_SLOPE * v.w;
    float4 ex;
    ex.x = __expf(v.x); ex.y = __expf(v.y);
    ex.z = __expf(v.z); ex.w = __expf(v.w);
    *(float4*)(g_e + (size_t)e * HEADS) = ex;
    atomicAdd(&g_denom[d * HEADS + 0], ex.x);
    atomicAdd(&g_denom[d * HEADS + 1], ex.y);
    atomicAdd(&g_denom[d * HEADS + 2], ex.z);
    atomicAdd(&g_denom[d * HEADS + 3], ex.w);
}

// ---------------- scan (counts -> exclusive offsets) ----------------------
__global__ void scan1_kernel() {
    __shared__ int s[1024];
    int t = threadIdx.x;
    int idx = blockIdx.x * 1024 + t;
    int v = (idx < N_NODES) ? g_counts[idx] : 0;
    s[t] = v;
    __syncthreads();
#pragma unroll
    for (int off = 1; off < 1024; off <<= 1) {
        int u = (t >= off) ? s[t - off] : 0;
        __syncthreads();
        s[t] += u;
        __syncthreads();
    }
    if (idx < N_NODES) g_offsets[idx] = s[t] - v;
    if (t == 1023) g_block_sums[blockIdx.x] = s[t];
}

__global__ void scan2_kernel(int nblocks) {
    __shared__ int s[128];
    int t = threadIdx.x;
    int v = (t < nblocks) ? g_block_sums[t] : 0;
    s[t] = v;
    __syncthreads();
#pragma unroll
    for (int off = 1; off < 128; off <<= 1) {
        int u = (t >= off) ? s[t - off] : 0;
        __syncthreads();
        s[t] += u;
        __syncthreads();
    }
    if (t < nblocks) g_block_sums[t] = s[t] - v;
}

__global__ void scan3_kernel() {
    int idx = blockIdx.x * 1024 + threadIdx.x;
    if (idx < N_NODES) {
        int off = g_offsets[idx] + g_block_sums[blockIdx.x];
        g_offsets[idx] = off;
        g_cursor[idx] = off;
    }
    if (idx == 0) g_offsets[N_NODES] = N_EDGES;
}

// ---------------- CSR scatter ---------------------------------------------
__global__ void scatter_kernel(const int* __restrict__ dst) {
    int e = blockIdx.x * blockDim.x + threadIdx.x;
    if (e >= N_EDGES) return;
    int pos = atomicAdd(&g_cursor[dst[e]], 1);
    g_edge_idx[pos] = e;
}

// ---- aggregation: rst[v] = sum a*ft[src], a = ex/denom, also writes a_out --
__global__ void agg_kernel(const int* __restrict__ src,
                           float* __restrict__ rst,
                           float* __restrict__ a_out, int has_a)
{
    int warp = (blockIdx.x * blockDim.x + threadIdx.x) >> 5;
    int lane = threadIdx.x & 31;
    if (warp >= N_NODES) return;
    int h = lane >> 3;
    int p0 = g_offsets[warp];
    int p1 = g_offsets[warp + 1];
    float4 acc = make_float4(0.f, 0.f, 0.f, 0.f);
    if (p1 > p0) {
        float rdenom = 1.0f / g_denom[warp * HEADS + h];
        const float4* ft4 = (const float4*)g_ft;
        for (int p = p0; p < p1; p++) {
            int e = g_edge_idx[p];
            int s = src[e];
            float a = g_e[(size_t)e * HEADS + h] * rdenom;
            if (has_a && (lane & 7) == 0) a_out[(size_t)e * HEADS + h] = a;
            float4 f = ft4[(size_t)s * 32 + lane];
            acc.x += a * f.x; acc.y += a * f.y;
            acc.z += a * f.z; acc.w += a * f.w;
        }
    }
    *(float4*)(rst + (size_t)warp * HD + lane * 4) = acc;
}

// ---------------- launch ----------------------------------------------------
extern "C" void kernel_launch(void* const* d_in, const int* in_sizes, int n_in,
                              void* d_out, int out_size)
{
    const float* feat   = (const float*)d_in[0];
    const float* W      = (const float*)d_in[1];
    const float* attn_l = (const float*)d_in[2];
    const float* attn_r = (const float*)d_in[3];
    const int*   src    = (const int*)d_in[4];
    const int*   dst    = (const int*)d_in[5];
    float* out = (float*)d_out;

    const int rst_elems = N_NODES * HD;
    const int has_a = (out_size >= rst_elems + N_EDGES * HEADS) ? 1 : 0;
    float* a_out = out + rst_elems;

    float* ft_dev;   cudaGetSymbolAddress((void**)&ft_dev, g_ft);

    init_kernel<<<(N_NODES * HEADS + 255) / 256, 256>>>();
    gemm_tf32_kernel<<<(N_NODES + 127) / 128, 256>>>(feat, W, ft_dev);
    elr_kernel<<<(N_NODES * 32 + 255) / 256, 256>>>(attn_l, attn_r);

    int eb = (N_EDGES + 255) / 256;
    edge_fused_kernel<<<eb, 256>>>(src, dst);

    int sb = (N_NODES + 1023) / 1024;      // 98
    scan1_kernel<<<sb, 1024>>>();
    scan2_kernel<<<1, 128>>>(sb);
    scan3_kernel<<<sb, 1024>>>();
    scatter_kernel<<<eb, 256>>>(dst);

    agg_kernel<<<(N_NODES * 32 + 255) / 256, 256>>>(src, out, a_out, has_a);
}

// round 4
// speedup vs baseline: 1.7603x; 1.0899x over previous
#include <cuda_runtime.h>
#include <cuda_bf16.h>
#include <math.h>

#define N_NODES 100000
#define N_EDGES 640000
#define IN_FEATS 256
#define HEADS 4
#define OUT_FEATS 32
#define HD (HEADS * OUT_FEATS)   // 128
#define NEG_SLOPE 0.2f

// ---------------- scratch (no allocs allowed) ----------------
__device__ float    g_ft[(size_t)N_NODES * HD];        // 51.2 MB
__device__ float    g_el[N_NODES * HEADS];
__device__ float    g_er[N_NODES * HEADS];
__device__ float    g_e [(size_t)N_EDGES * HEADS];     // exp(logit), CSR order
__device__ int      g_counts[N_NODES];
__device__ int      g_offsets[N_NODES + 1];
__device__ int      g_cursor[N_NODES];
__device__ int      g_block_sums[128];
__device__ int      g_edge_idx[N_EDGES];               // CSR pos -> edge id
__device__ int      g_csr_src[N_EDGES];                // CSR pos -> src node

// ---------------- TF32 helpers ----------------
__device__ __forceinline__ float to_tf32(float x) {
    unsigned u;
    asm("cvt.rna.tf32.f32 %0, %1;" : "=r"(u) : "f"(x));
    return __uint_as_float(u);
}

__device__ __forceinline__ void mma_tf32(float* d, const unsigned* a,
                                         unsigned b0, unsigned b1) {
    asm volatile(
        "mma.sync.aligned.m16n8k8.row.col.f32.tf32.tf32.f32 "
        "{%0,%1,%2,%3}, {%4,%5,%6,%7}, {%8,%9}, {%0,%1,%2,%3};"
        : "+f"(d[0]), "+f"(d[1]), "+f"(d[2]), "+f"(d[3])
        : "r"(a[0]), "r"(a[1]), "r"(a[2]), "r"(a[3]), "r"(b0), "r"(b1));
}

// ---- GEMM (TF32 MMA) + fused el/er epilogue -------------------------------
// 128x128 tile, BK=32, 256 threads = 8 warps (4x2), register double-buffer.
__global__ __launch_bounds__(256) void gemm_tf32_kernel(
    const float* __restrict__ A, const float* __restrict__ B,
    const float* __restrict__ attn_l, const float* __restrict__ attn_r,
    float* __restrict__ C)
{
    __shared__ float As[128][36];   // [m][k] pad->conflict-free frag loads
    __shared__ float Bs[32][136];   // [k][n]
    const int tid  = threadIdx.x;
    const int warp = tid >> 5, lane = tid & 31;
    const int wm = warp >> 1, wn = warp & 1;      // warp tile (wm*32, wn*64)
    const int g = lane >> 2, c = lane & 3;
    const int blockM = blockIdx.x * 128;

    float acc[2][8][4];
#pragma unroll
    for (int i = 0; i < 2; i++)
#pragma unroll
        for (int j = 0; j < 8; j++)
#pragma unroll
            for (int r = 0; r < 4; r++) acc[i][j][r] = 0.0f;

    const int arow = tid >> 1;             // 0..127
    const int akq  = (tid & 1) * 16;       // 0 or 16
    const bool arow_ok = (blockM + arow) < N_NODES;
    const float* aptr = A + (size_t)(blockM + arow) * IN_FEATS + akq;

    float4 ra[4], rb[4];
#pragma unroll
    for (int i = 0; i < 4; i++)
        ra[i] = arow_ok ? *(const float4*)(aptr + i * 4)
                        : make_float4(0.f, 0.f, 0.f, 0.f);
#pragma unroll
    for (int it = 0; it < 4; it++) {
        int f = tid + it * 256;
        rb[it] = *(const float4*)(B + (size_t)(f >> 5) * HD + (f & 31) * 4);
    }

    for (int k0 = 0; k0 < IN_FEATS; k0 += 32) {
#pragma unroll
        for (int i = 0; i < 4; i++) {
            As[arow][akq + i * 4 + 0] = to_tf32(ra[i].x);
            As[arow][akq + i * 4 + 1] = to_tf32(ra[i].y);
            As[arow][akq + i * 4 + 2] = to_tf32(ra[i].z);
            As[arow][akq + i * 4 + 3] = to_tf32(ra[i].w);
        }
#pragma unroll
        for (int it = 0; it < 4; it++) {
            int f = tid + it * 256;
            int kr = f >> 5, cq = (f & 31) * 4;
            Bs[kr][cq + 0] = to_tf32(rb[it].x);
            Bs[kr][cq + 1] = to_tf32(rb[it].y);
            Bs[kr][cq + 2] = to_tf32(rb[it].z);
            Bs[kr][cq + 3] = to_tf32(rb[it].w);
        }
        __syncthreads();

        if (k0 + 32 < IN_FEATS) {
#pragma unroll
            for (int i = 0; i < 4; i++)
                ra[i] = arow_ok ? *(const float4*)(aptr + k0 + 32 + i * 4)
                                : make_float4(0.f, 0.f, 0.f, 0.f);
#pragma unroll
            for (int it = 0; it < 4; it++) {
                int f = tid + it * 256;
                rb[it] = *(const float4*)(B + (size_t)(k0 + 32 + (f >> 5)) * HD
                                          + (f & 31) * 4);
            }
        }

#pragma unroll
        for (int ks = 0; ks < 4; ks++) {
            const int kb = ks * 8;
            unsigned afrag[2][4];
#pragma unroll
            for (int i = 0; i < 2; i++) {
                int r = wm * 32 + i * 16;
                afrag[i][0] = __float_as_uint(As[r + g    ][kb + c    ]);
                afrag[i][1] = __float_as_uint(As[r + g + 8][kb + c    ]);
                afrag[i][2] = __float_as_uint(As[r + g    ][kb + c + 4]);
                afrag[i][3] = __float_as_uint(As[r + g + 8][kb + c + 4]);
            }
#pragma unroll
            for (int j = 0; j < 8; j++) {
                int col = wn * 64 + j * 8 + g;
                unsigned b0 = __float_as_uint(Bs[kb + c    ][col]);
                unsigned b1 = __float_as_uint(Bs[kb + c + 4][col]);
                mma_tf32(acc[0][j], afrag[0], b0, b1);
                mma_tf32(acc[1][j], afrag[1], b0, b1);
            }
        }
        __syncthreads();
    }

    // --- epilogue 1: store ft ---
#pragma unroll
    for (int i = 0; i < 2; i++) {
        int r0 = blockM + wm * 32 + i * 16 + g;
#pragma unroll
        for (int j = 0; j < 8; j++) {
            int cc = wn * 64 + j * 8 + c * 2;
            if (r0 < N_NODES)
                *(float2*)(C + (size_t)r0 * HD + cc) =
                    make_float2(acc[i][j][0], acc[i][j][1]);
            if (r0 + 8 < N_NODES)
                *(float2*)(C + (size_t)(r0 + 8) * HD + cc) =
                    make_float2(acc[i][j][2], acc[i][j][3]);
        }
    }

    // --- epilogue 2: el/er. wn=0 -> heads 0,1 ; wn=1 -> heads 2,3.
    float elp[4][2], erp[4][2];
#pragma unroll
    for (int rs = 0; rs < 4; rs++)
#pragma unroll
        for (int hl = 0; hl < 2; hl++) { elp[rs][hl] = 0.f; erp[rs][hl] = 0.f; }
#pragma unroll
    for (int i = 0; i < 2; i++)
#pragma unroll
        for (int j = 0; j < 8; j++)
#pragma unroll
            for (int r = 0; r < 4; r++) {
                int col = wn * 64 + j * 8 + c * 2 + (r & 1);
                float wl = __ldg(attn_l + col);   // attn flat [H*D] == col
                float wr = __ldg(attn_r + col);
                int rs = i * 2 + (r >> 1);
                elp[rs][j >> 2] += acc[i][j][r] * wl;
                erp[rs][j >> 2] += acc[i][j][r] * wr;
            }
#pragma unroll
    for (int rs = 0; rs < 4; rs++)
#pragma unroll
        for (int hl = 0; hl < 2; hl++) {
#pragma unroll
            for (int o = 1; o <= 2; o <<= 1) {
                elp[rs][hl] += __shfl_xor_sync(0xffffffffu, elp[rs][hl], o);
                erp[rs][hl] += __shfl_xor_sync(0xffffffffu, erp[rs][hl], o);
            }
        }
    if (c == 0) {
#pragma unroll
        for (int rs = 0; rs < 4; rs++) {
            int row = blockM + wm * 32 + (rs >> 1) * 16 + (rs & 1) * 8 + g;
            if (row < N_NODES) {
#pragma unroll
                for (int hl = 0; hl < 2; hl++) {
                    int h = wn * 2 + hl;
                    g_el[row * HEADS + h] = elp[rs][hl];
                    g_er[row * HEADS + h] = erp[rs][hl];
                }
            }
        }
    }
}

// ---------------- histogram (int4 vectorized) -------------------------------
__global__ void hist_kernel(const int* __restrict__ dst) {
    int i = blockIdx.x * blockDim.x + threadIdx.x;
    if (i >= N_EDGES / 4) return;
    int4 d = ((const int4*)dst)[i];
    atomicAdd(&g_counts[d.x], 1);
    atomicAdd(&g_counts[d.y], 1);
    atomicAdd(&g_counts[d.z], 1);
    atomicAdd(&g_counts[d.w], 1);
}

// ---------------- scan (counts -> exclusive offsets) ------------------------
__global__ void scan1_kernel() {
    __shared__ int s[1024];
    int t = threadIdx.x;
    int idx = blockIdx.x * 1024 + t;
    int v = (idx < N_NODES) ? g_counts[idx] : 0;
    s[t] = v;
    __syncthreads();
#pragma unroll
    for (int off = 1; off < 1024; off <<= 1) {
        int u = (t >= off) ? s[t - off] : 0;
        __syncthreads();
        s[t] += u;
        __syncthreads();
    }
    if (idx < N_NODES) g_offsets[idx] = s[t] - v;
    if (t == 1023) g_block_sums[blockIdx.x] = s[t];
}

__global__ void scan2_kernel(int nblocks) {
    __shared__ int s[128];
    int t = threadIdx.x;
    int v = (t < nblocks) ? g_block_sums[t] : 0;
    s[t] = v;
    __syncthreads();
#pragma unroll
    for (int off = 1; off < 128; off <<= 1) {
        int u = (t >= off) ? s[t - off] : 0;
        __syncthreads();
        s[t] += u;
        __syncthreads();
    }
    if (t < nblocks) g_block_sums[t] = s[t] - v;
}

__global__ void scan3_kernel() {
    int idx = blockIdx.x * 1024 + threadIdx.x;
    if (idx < N_NODES) {
        int off = g_offsets[idx] + g_block_sums[blockIdx.x];
        g_offsets[idx] = off;
        g_cursor[idx] = off;
    }
    if (idx == 0) g_offsets[N_NODES] = N_EDGES;
}

// ---------------- CSR scatter (stores edge id AND src) ----------------------
__global__ void scatter_kernel(const int* __restrict__ src,
                               const int* __restrict__ dst) {
    int e = blockIdx.x * blockDim.x + threadIdx.x;
    if (e >= N_EDGES) return;
    int pos = atomicAdd(&g_cursor[dst[e]], 1);
    g_edge_idx[pos] = e;
    g_csr_src[pos]  = src[e];
}

// ---- fused softmax + aggregation: one warp per dst node, zero atomics ------
// lane l owns output floats [4l, 4l+4); head h = l>>3.
// FIX vs prev round: per-edge exp values are staged in a per-warp smem buffer
// so each lane reads edge q's exp FOR ITS OWN HEAD (shuffle version delivered
// the sender's head instead -> scrambled heads).
__global__ __launch_bounds__(256) void agg_fused_kernel(
    float* __restrict__ rst, float* __restrict__ a_out, int has_a)
{
    __shared__ float ex_s[8][32][4];   // [warp][edge-in-chunk][head]
    int warp = (blockIdx.x * blockDim.x + threadIdx.x) >> 5;
    int lane = threadIdx.x & 31;
    int wlocal = (threadIdx.x >> 5);
    if (warp >= N_NODES) return;
    const int h = lane >> 3;
    const int p0 = g_offsets[warp];
    const int p1 = g_offsets[warp + 1];

    float4 er4 = *(const float4*)(g_er + (size_t)warp * HEADS);
    float4 acc = make_float4(0.f, 0.f, 0.f, 0.f);
    float4 den = make_float4(0.f, 0.f, 0.f, 0.f);
    const float4* ft4 = (const float4*)g_ft;

    for (int base = p0; base < p1; base += 32) {
        int p = base + lane;
        float4 ex4 = make_float4(0.f, 0.f, 0.f, 0.f);
        int s = 0;
        if (p < p1) {
            s = g_csr_src[p];
            float4 el4 = *(const float4*)(g_el + (size_t)s * HEADS);
            float4 v;
            v.x = el4.x + er4.x; v.y = el4.y + er4.y;
            v.z = el4.z + er4.z; v.w = el4.w + er4.w;
            v.x = v.x > 0.f ? v.x : NEG_SLOPE * v.x;
            v.y = v.y > 0.f ? v.y : NEG_SLOPE * v.y;
            v.z = v.z > 0.f ? v.z : NEG_SLOPE * v.z;
            v.w = v.w > 0.f ? v.w : NEG_SLOPE * v.w;
            ex4.x = __expf(v.x); ex4.y = __expf(v.y);
            ex4.z = __expf(v.z); ex4.w = __expf(v.w);
            if (has_a) *(float4*)(g_e + (size_t)p * HEADS) = ex4;
        }
        den.x += ex4.x; den.y += ex4.y; den.z += ex4.z; den.w += ex4.w;

        __syncwarp();                      // protect prior-iter reads
        *(float4*)&ex_s[wlocal][lane][0] = ex4;
        __syncwarp();                      // make stores visible

        int cnt = min(p1 - base, 32);
        for (int q = 0; q < cnt; q++) {
            float exq = ex_s[wlocal][q][h];               // edge q, MY head
            int   sq  = __shfl_sync(0xffffffffu, s, q);   // head-independent
            float4 f = ft4[(size_t)sq * 32 + lane];
            acc.x += exq * f.x; acc.y += exq * f.y;
            acc.z += exq * f.z; acc.w += exq * f.w;
        }
    }

#pragma unroll
    for (int o = 16; o >= 1; o >>= 1) {
        den.x += __shfl_xor_sync(0xffffffffu, den.x, o);
        den.y += __shfl_xor_sync(0xffffffffu, den.y, o);
        den.z += __shfl_xor_sync(0xffffffffu, den.z, o);
        den.w += __shfl_xor_sync(0xffffffffu, den.w, o);
    }

    if (p1 > p0) {
        float4 rd4 = make_float4(1.f / den.x, 1.f / den.y,
                                 1.f / den.z, 1.f / den.w);
        float rdh = (h == 0) ? rd4.x : (h == 1) ? rd4.y
                  : (h == 2) ? rd4.z : rd4.w;
        acc.x *= rdh; acc.y *= rdh; acc.z *= rdh; acc.w *= rdh;
        *(float4*)(rst + (size_t)warp * HD + lane * 4) = acc;
        if (has_a) {
            for (int p = p0 + lane; p < p1; p += 32) {
                float4 ex4 = *(const float4*)(g_e + (size_t)p * HEADS);
                int e = g_edge_idx[p];
                float4 a4 = make_float4(ex4.x * rd4.x, ex4.y * rd4.y,
                                        ex4.z * rd4.z, ex4.w * rd4.w);
                *(float4*)(a_out + (size_t)e * HEADS) = a4;
            }
        }
    } else {
        *(float4*)(rst + (size_t)warp * HD + lane * 4) =
            make_float4(0.f, 0.f, 0.f, 0.f);
    }
}

// ---------------- launch ------------------------------------------------------
extern "C" void kernel_launch(void* const* d_in, const int* in_sizes, int n_in,
                              void* d_out, int out_size)
{
    const float* feat   = (const float*)d_in[0];
    const float* W      = (const float*)d_in[1];
    const float* attn_l = (const float*)d_in[2];
    const float* attn_r = (const float*)d_in[3];
    const int*   src    = (const int*)d_in[4];
    const int*   dst    = (const int*)d_in[5];
    float* out = (float*)d_out;

    const int rst_elems = N_NODES * HD;
    const int has_a = (out_size >= rst_elems + N_EDGES * HEADS) ? 1 : 0;
    float* a_out = out + rst_elems;

    float* ft_dev;     cudaGetSymbolAddress((void**)&ft_dev, g_ft);
    int*   counts_dev; cudaGetSymbolAddress((void**)&counts_dev, g_counts);

    cudaMemsetAsync(counts_dev, 0, N_NODES * sizeof(int));

    gemm_tf32_kernel<<<(N_NODES + 127) / 128, 256>>>(feat, W, attn_l, attn_r,
                                                     ft_dev);
    hist_kernel<<<(N_EDGES / 4 + 255) / 256, 256>>>(dst);

    int sb = (N_NODES + 1023) / 1024;      // 98
    scan1_kernel<<<sb, 1024>>>();
    scan2_kernel<<<1, 128>>>(sb);
    scan3_kernel<<<sb, 1024>>>();

    scatter_kernel<<<(N_EDGES + 255) / 256, 256>>>(src, dst);

    agg_fused_kernel<<<(N_NODES * 32 + 255) / 256, 256>>>(out, a_out, has_a);
}